// round 7
// baseline (speedup 1.0000x reference)
#include <cuda_runtime.h>
#include <cuda_bf16.h>
#include <math.h>
#include <cstdint>

#define SDIM 4096
#define CDIM 256
#define EDIM 128
#define NBATCH 4

// ---- scratch (device globals: allocation-free) ----
__device__ uint16_t      g_tp8[(size_t)NBATCH * SDIM * 128];       // e4m3 pairs: [s][0:64)=theta, [64:128)=phi (b16 units)
__device__ uint16_t      g_f8 [(size_t)NBATCH * SDIM * 2048];      // e4m3 pairs: unnormalized exp(logits), row = 2048 b16
__device__ __nv_bfloat16 g_xb [(size_t)NBATCH * CDIM * SDIM];      // x bf16 [n][c][s] (for thetaphi)
__device__ uint16_t      g_x8 [(size_t)NBATCH * CDIM * 2048];      // x e4m3 [n][c][s] (pairs, for attend)
__device__ __nv_bfloat16 g_yb [(size_t)NBATCH * SDIM * CDIM];      // y bf16 [n][s][c]
__device__ __nv_bfloat16 g_w2[256 * 256];                          // rows 0-127 theta_w, 128-255 phi_w (bf16)
__device__ __nv_bfloat16 g_w3[256 * 256];                          // proj_w bf16 [o][c]
__device__ float         g_Z [(size_t)NBATCH * SDIM];              // row sums

// ============================ low-level helpers ============================
__device__ __forceinline__ uint32_t smem_u32(const void* p) {
    uint32_t a;
    asm("{ .reg .u64 t; cvta.to.shared.u64 t, %1; cvt.u32.u64 %0, t; }" : "=r"(a) : "l"(p));
    return a;
}
__device__ __forceinline__ void ldsm4(uint32_t r[4], uint32_t addr) {
    asm volatile("ldmatrix.sync.aligned.m8n8.x4.shared.b16 {%0,%1,%2,%3}, [%4];"
                 : "=r"(r[0]), "=r"(r[1]), "=r"(r[2]), "=r"(r[3]) : "r"(addr));
}
__device__ __forceinline__ void ldsm4t(uint32_t r[4], uint32_t addr) {
    asm volatile("ldmatrix.sync.aligned.m8n8.x4.trans.shared.b16 {%0,%1,%2,%3}, [%4];"
                 : "=r"(r[0]), "=r"(r[1]), "=r"(r[2]), "=r"(r[3]) : "r"(addr));
}
__device__ __forceinline__ void mma16816(float c[4], const uint32_t a[4], uint32_t b0, uint32_t b1) {
    asm volatile("mma.sync.aligned.m16n8k16.row.col.f32.bf16.bf16.f32 "
                 "{%0,%1,%2,%3},{%4,%5,%6,%7},{%8,%9},{%0,%1,%2,%3};"
                 : "+f"(c[0]), "+f"(c[1]), "+f"(c[2]), "+f"(c[3])
                 : "r"(a[0]), "r"(a[1]), "r"(a[2]), "r"(a[3]), "r"(b0), "r"(b1));
}
// FP8 e4m3 mma: m16n8k32. Fragment layout = byte-pair-isomorphic to m16n8k16 bf16.
__device__ __forceinline__ void mma16832f8(float c[4], const uint32_t a[4], uint32_t b0, uint32_t b1) {
    asm volatile("mma.sync.aligned.m16n8k32.row.col.f32.e4m3.e4m3.f32 "
                 "{%0,%1,%2,%3},{%4,%5,%6,%7},{%8,%9},{%0,%1,%2,%3};"
                 : "+f"(c[0]), "+f"(c[1]), "+f"(c[2]), "+f"(c[3])
                 : "r"(a[0]), "r"(a[1]), "r"(a[2]), "r"(a[3]), "r"(b0), "r"(b1));
}
__device__ __forceinline__ void cp16(uint32_t saddr, const void* g) {
    asm volatile("cp.async.cg.shared.global [%0], [%1], 16;" :: "r"(saddr), "l"(g));
}
#define CP_COMMIT() asm volatile("cp.async.commit_group;" ::: "memory")
#define CP_WAIT(N)  asm volatile("cp.async.wait_group %0;" :: "n"(N) : "memory")

// pack two floats -> e4m3x2 (lo in low byte)
__device__ __forceinline__ uint16_t pack_e4m3(float lo, float hi) {
    uint16_t r;
    asm("cvt.rn.satfinite.e4m3x2.f32 %0, %1, %2;" : "=h"(r) : "f"(hi), "f"(lo));
    return r;
}

// R rows x 64 b16-cols (128B rows), XOR-16B swizzle keyed on row&7. NT threads.
// For fp8 tiles a "b16 col" = 2 fp8 along K; ldg is row stride in b16 units.
template<int R, int NT>
__device__ __forceinline__ void load_tileT(uint32_t sdst, const uint16_t* g, int ldg) {
    const int tid = threadIdx.x;
    #pragma unroll
    for (int i = 0; i < (R * 8) / NT; i++) {
        const int c = tid + i * NT;
        const int r = c >> 3, kc = c & 7;
        const uint32_t so = sdst + r * 128 + (((uint32_t)kc * 16) ^ ((r & 7) * 16));
        cp16(so, g + (size_t)r * ldg + kc * 8);
    }
}
// 64 rows x 128 b16-cols (256B rows), 256 threads (trans-A path, bf16).
__device__ __forceinline__ void load_tile_64x128(uint32_t sdst, const __nv_bfloat16* g, int ldg) {
    const int tid = threadIdx.x;
    #pragma unroll
    for (int i = 0; i < 4; i++) {
        const int c = tid + i * 256;
        const int r = c >> 4, kc = c & 15;
        const uint32_t so = sdst + r * 256 + (((uint32_t)kc * 16) ^ ((r & 7) * 16));
        cp16(so, g + (size_t)r * ldg + kc * 8);
    }
}

// ---- bf16 64x32 warp-tile chunk (small GEMMs) ----
__device__ __forceinline__ void compute_chunk(uint32_t sA, uint32_t sB,
                                              int m_base, int n_base, int lane,
                                              float acc[4][4][4]) {
    #pragma unroll
    for (int ks = 0; ks < 4; ks++) {
        const int kc = ks * 2 + (lane >> 4);
        uint32_t a[4][4];
        #pragma unroll
        for (int mi = 0; mi < 4; mi++) {
            const int row = m_base + mi * 16 + (lane & 15);
            ldsm4(a[mi], sA + row * 128 + (((uint32_t)kc * 16) ^ ((row & 7) * 16)));
        }
        uint32_t b[4][2];
        #pragma unroll
        for (int nh = 0; nh < 2; nh++) {
            const int row = n_base + nh * 16 + (lane & 15);
            uint32_t r4[4];
            ldsm4(r4, sB + row * 128 + (((uint32_t)kc * 16) ^ ((row & 7) * 16)));
            b[nh * 2 + 0][0] = r4[0]; b[nh * 2 + 0][1] = r4[2];
            b[nh * 2 + 1][0] = r4[1]; b[nh * 2 + 1][1] = r4[3];
        }
        #pragma unroll
        for (int mi = 0; mi < 4; mi++)
            #pragma unroll
            for (int ni = 0; ni < 4; ni++)
                mma16816(acc[mi][ni], a[mi], b[ni][0], b[ni][1]);
    }
}

// ---- FP8 64x64 warp-tile chunk: 8 LDSM -> 32 MMA per ks, k=32 fp8 per ks ----
// Tile = 128B rows = 128 fp8 K per chunk. Addressing identical to bf16 path.
__device__ __forceinline__ void compute_chunk64f8(uint32_t sA, uint32_t sB,
                                                  int m_base, int n_base, int lane,
                                                  float acc[4][8][4]) {
    #pragma unroll
    for (int ks = 0; ks < 4; ks++) {
        const int kc = ks * 2 + (lane >> 4);
        uint32_t a[4][4];
        #pragma unroll
        for (int mi = 0; mi < 4; mi++) {
            const int row = m_base + mi * 16 + (lane & 15);
            ldsm4(a[mi], sA + row * 128 + (((uint32_t)kc * 16) ^ ((row & 7) * 16)));
        }
        uint32_t b[8][2];
        #pragma unroll
        for (int nh = 0; nh < 4; nh++) {
            const int row = n_base + nh * 16 + (lane & 15);
            uint32_t r4[4];
            ldsm4(r4, sB + row * 128 + (((uint32_t)kc * 16) ^ ((row & 7) * 16)));
            b[nh * 2 + 0][0] = r4[0]; b[nh * 2 + 0][1] = r4[2];
            b[nh * 2 + 1][0] = r4[1]; b[nh * 2 + 1][1] = r4[3];
        }
        #pragma unroll
        for (int mi = 0; mi < 4; mi++)
            #pragma unroll
            for (int ni = 0; ni < 8; ni++)
                mma16832f8(acc[mi][ni], a[mi], b[ni][0], b[ni][1]);
    }
}

// trans-A chunk (thetaphi, bf16)
__device__ __forceinline__ void compute_chunk_At(uint32_t sA, uint32_t sB,
                                                 int wm, int wn, int lane,
                                                 float acc[4][4][4]) {
    #pragma unroll
    for (int ks = 0; ks < 4; ks++) {
        uint32_t a[4][4];
        const int crow_l = ks * 16 + (lane & 7) + ((lane >> 4) & 1) * 8;
        #pragma unroll
        for (int mi = 0; mi < 4; mi++) {
            const int scol = wm * 64 + mi * 16 + ((lane >> 3) & 1) * 8;
            ldsm4t(a[mi], sA + crow_l * 256 + ((((uint32_t)scol >> 3) * 16) ^ ((crow_l & 7) * 16)));
        }
        const int kc = ks * 2 + (lane >> 4);
        uint32_t b[4][2];
        #pragma unroll
        for (int nh = 0; nh < 2; nh++) {
            const int row = wn * 32 + nh * 16 + (lane & 15);
            uint32_t r4[4];
            ldsm4(r4, sB + row * 128 + (((uint32_t)kc * 16) ^ ((row & 7) * 16)));
            b[nh * 2 + 0][0] = r4[0]; b[nh * 2 + 0][1] = r4[2];
            b[nh * 2 + 1][0] = r4[1]; b[nh * 2 + 1][1] = r4[3];
        }
        #pragma unroll
        for (int mi = 0; mi < 4; mi++)
            #pragma unroll
            for (int ni = 0; ni < 4; ni++)
                mma16816(acc[mi][ni], a[mi], b[ni][0], b[ni][1]);
    }
}

#define ZERO_ACC4(acc) do { \
    _Pragma("unroll") for (int _a = 0; _a < 4; _a++) \
    _Pragma("unroll") for (int _b = 0; _b < 4; _b++) \
    _Pragma("unroll") for (int _c = 0; _c < 4; _c++) acc[_a][_b][_c] = 0.0f; } while (0)
#define ZERO_ACC8(acc) do { \
    _Pragma("unroll") for (int _a = 0; _a < 4; _a++) \
    _Pragma("unroll") for (int _b = 0; _b < 8; _b++) \
    _Pragma("unroll") for (int _c = 0; _c < 4; _c++) acc[_a][_b][_c] = 0.0f; } while (0)

// ============================ prep ============================
__global__ __launch_bounds__(256) void prep_bf16(const float4* __restrict__ x,
                                                 const float4* __restrict__ theta_w,
                                                 const float4* __restrict__ phi_w,
                                                 const float4* __restrict__ proj_w,
                                                 uint2* __restrict__ xb,
                                                 uint32_t* __restrict__ x8,
                                                 uint2* __restrict__ w2,
                                                 uint2* __restrict__ w3,
                                                 float* __restrict__ Z, int n4)
{
    const int gt = blockIdx.x * blockDim.x + threadIdx.x;
    const int stride = gridDim.x * blockDim.x;
    if (gt < NBATCH * SDIM) Z[gt] = 0.0f;
    for (int i = gt; i < n4; i += stride) {
        float4 v = x[i];
        __nv_bfloat162 a = __floats2bfloat162_rn(v.x, v.y);
        __nv_bfloat162 b = __floats2bfloat162_rn(v.z, v.w);
        xb[i] = make_uint2(*reinterpret_cast<uint32_t*>(&a), *reinterpret_cast<uint32_t*>(&b));
        const uint32_t lo = pack_e4m3(v.x, v.y);
        const uint32_t hi = pack_e4m3(v.z, v.w);
        x8[i] = lo | (hi << 16);
    }
    if (gt < 8192) {
        float4 v = theta_w[gt];
        __nv_bfloat162 a = __floats2bfloat162_rn(v.x, v.y);
        __nv_bfloat162 b = __floats2bfloat162_rn(v.z, v.w);
        w2[gt] = make_uint2(*reinterpret_cast<uint32_t*>(&a), *reinterpret_cast<uint32_t*>(&b));
        v = phi_w[gt];
        a = __floats2bfloat162_rn(v.x, v.y);
        b = __floats2bfloat162_rn(v.z, v.w);
        w2[8192 + gt] = make_uint2(*reinterpret_cast<uint32_t*>(&a), *reinterpret_cast<uint32_t*>(&b));
    }
    if (gt < 16384) {
        float4 v = proj_w[gt];
        __nv_bfloat162 a = __floats2bfloat162_rn(v.x, v.y);
        __nv_bfloat162 b = __floats2bfloat162_rn(v.z, v.w);
        w3[gt] = make_uint2(*reinterpret_cast<uint32_t*>(&a), *reinterpret_cast<uint32_t*>(&b));
    }
}

// ============================ theta/phi projection (bf16 HMMA trans-A -> e4m3 out) ============================
#define SA2(st) ((uint32_t)((st) * 32768))
#define SB2(st) ((uint32_t)((st) * 32768 + 16384))
__global__ __launch_bounds__(256)
void thetaphi_hmma(const __nv_bfloat16* __restrict__ xb,
                   const __nv_bfloat16* __restrict__ w2,
                   uint16_t* __restrict__ tp8)
{
    extern __shared__ char smem[];
    const uint32_t sb = smem_u32(smem);
    const int tid = threadIdx.x, lane = tid & 31, wid = tid >> 5;
    const int wm = wid & 1, wn = wid >> 1;
    const int z = blockIdx.z, m0 = blockIdx.y * 128, n0 = blockIdx.x * 128;

    const __nv_bfloat16* Abase = xb + (size_t)z * CDIM * SDIM + m0;
    const __nv_bfloat16* Bbase = w2 + (size_t)n0 * 256;

    float acc[4][4][4];
    ZERO_ACC4(acc);

    load_tile_64x128(sb + SA2(0), Abase, SDIM);
    load_tileT<128, 256>(sb + SB2(0), (const uint16_t*)Bbase, 256);
    CP_COMMIT();

    const int KT = 4;
    #pragma unroll
    for (int kt = 0; kt < KT; kt++) {
        if (kt + 1 < KT) {
            load_tile_64x128(sb + SA2((kt + 1) & 1), Abase + (size_t)(kt + 1) * 64 * SDIM, SDIM);
            load_tileT<128, 256>(sb + SB2((kt + 1) & 1), (const uint16_t*)(Bbase + (kt + 1) * 64), 256);
            CP_COMMIT();
            CP_WAIT(1);
        } else {
            CP_WAIT(0);
        }
        __syncthreads();
        compute_chunk_At(sb + SA2(kt & 1), sb + SB2(kt & 1), wm, wn, lane, acc);
        __syncthreads();
    }

    // epilogue: pack e4m3 pairs. tp8 row = 128 b16 (256 fp8): theta cols 0-63, phi 64-127.
    const int lrow = lane >> 2, lcol2 = (lane & 3) * 2;
    #pragma unroll
    for (int mi = 0; mi < 4; mi++) {
        const int gr0 = m0 + wm * 64 + mi * 16 + lrow;   // s-row
        #pragma unroll
        for (int ni = 0; ni < 4; ni++) {
            const int col = n0 + wn * 32 + ni * 8 + lcol2;  // o in [0,256), even
            tp8[((size_t)z * SDIM + gr0) * 128 + (col >> 1)] =
                pack_e4m3(acc[mi][ni][0], acc[mi][ni][1]);
            tp8[((size_t)z * SDIM + gr0 + 8) * 128 + (col >> 1)] =
                pack_e4m3(acc[mi][ni][2], acc[mi][ni][3]);
        }
    }
}

// ============================ fused logits + exp (FP8 HMMA, 128x256 tile, whole K resident) ============================
// smem: A(theta 128x64b16) @0 16KB, B(phi 256x64b16) @16384 32KB. 48KB total.
__global__ __launch_bounds__(256)
void logits_exp_f8(const uint16_t* __restrict__ tp8,
                   uint16_t* __restrict__ f8,
                   float* __restrict__ Z)
{
    extern __shared__ char smem[];
    const uint32_t sb = smem_u32(smem);
    const int tid = threadIdx.x, lane = tid & 31, wid = tid >> 5;
    const int wm = wid & 1, wn = wid >> 1;  // 2x4 grid of 64x64 warp tiles
    const int z = blockIdx.z, m0 = blockIdx.y * 128, n0 = blockIdx.x * 256;

    const uint16_t* Abase = tp8 + ((size_t)(z * SDIM + m0)) * 128;       // theta (cols 0-63)
    const uint16_t* Bbase = tp8 + ((size_t)(z * SDIM + n0)) * 128 + 64;  // phi (cols 64-127)

    float acc[4][8][4];
    ZERO_ACC8(acc);

    load_tileT<128, 256>(sb + 0,     Abase, 128);
    load_tileT<256, 256>(sb + 16384, Bbase, 128);
    CP_COMMIT();
    CP_WAIT(0);
    __syncthreads();

    compute_chunk64f8(sb + 0, sb + 16384, wm * 64, wn * 64, lane, acc);

    const float alpha = 0.08838834764831845f; // 1/sqrt(128)
    const int lrow = lane >> 2, lcol2 = (lane & 3) * 2;
    #pragma unroll
    for (int mi = 0; mi < 4; mi++) {
        const int gr0 = m0 + wm * 64 + mi * 16 + lrow;
        const int gr1 = gr0 + 8;
        float rs0 = 0.0f, rs1 = 0.0f;
        #pragma unroll
        for (int ni = 0; ni < 8; ni++) {
            const int col = n0 + wn * 64 + ni * 8 + lcol2;   // even
            float e00 = __expf(acc[mi][ni][0] * alpha);
            float e01 = __expf(acc[mi][ni][1] * alpha);
            float e10 = __expf(acc[mi][ni][2] * alpha);
            float e11 = __expf(acc[mi][ni][3] * alpha);
            rs0 += e00 + e01; rs1 += e10 + e11;
            f8[((size_t)z * SDIM + gr0) * 2048 + (col >> 1)] = pack_e4m3(e00, e01);
            f8[((size_t)z * SDIM + gr1) * 2048 + (col >> 1)] = pack_e4m3(e10, e11);
        }
        rs0 += __shfl_xor_sync(0xffffffffu, rs0, 1);
        rs0 += __shfl_xor_sync(0xffffffffu, rs0, 2);
        rs1 += __shfl_xor_sync(0xffffffffu, rs1, 1);
        rs1 += __shfl_xor_sync(0xffffffffu, rs1, 2);
        if ((lane & 3) == 0) {
            atomicAdd(&Z[(size_t)z * SDIM + gr0], rs0);
            atomicAdd(&Z[(size_t)z * SDIM + gr1], rs1);
        }
    }
}

// ============================ attend (FP8 HMMA, 128x256 tile, 3-stage, KT=32) ============================
// stage st: A(f 128x64b16) @st*49152 16KB, B(x8 256x64b16) @st*49152+16384 32KB. 144KB.
#define ASA(st) ((uint32_t)((st) * 49152))
#define ASB(st) ((uint32_t)((st) * 49152 + 16384))
__global__ __launch_bounds__(256)
void attend_f8(const uint16_t* __restrict__ f8,
               const uint16_t* __restrict__ x8,
               const float* __restrict__ Z,
               __nv_bfloat16* __restrict__ y)
{
    extern __shared__ char smem[];
    const uint32_t sb = smem_u32(smem);
    const int tid = threadIdx.x, lane = tid & 31, wid = tid >> 5;
    const int wm = wid & 1, wn = wid >> 1;  // 2x4 grid of 64x64 warp tiles
    const int z = blockIdx.z, m0 = blockIdx.y * 128;

    const uint16_t* Abase = f8 + ((size_t)z * SDIM + m0) * 2048;  // 128 rows, stride 2048 b16
    const uint16_t* Bbase = x8 + (size_t)z * CDIM * 2048;         // 256 rows, stride 2048 b16

    float acc[4][8][4];
    ZERO_ACC8(acc);

    load_tileT<128, 256>(sb + ASA(0), Abase, 2048);
    load_tileT<256, 256>(sb + ASB(0), Bbase, 2048);
    CP_COMMIT();
    load_tileT<128, 256>(sb + ASA(1), Abase + 64, 2048);
    load_tileT<256, 256>(sb + ASB(1), Bbase + 64, 2048);
    CP_COMMIT();

    const int KT = 32;  // 32 chunks x 128 fp8-K
    for (int kt = 0; kt < KT; kt++) {
        if (kt + 1 < KT) { CP_WAIT(1); } else { CP_WAIT(0); }
        __syncthreads();
        if (kt + 2 < KT) {
            const int st = (kt + 2) % 3;
            load_tileT<128, 256>(sb + ASA(st), Abase + (kt + 2) * 64, 2048);
            load_tileT<256, 256>(sb + ASB(st), Bbase + (kt + 2) * 64, 2048);
            CP_COMMIT();
        }
        compute_chunk64f8(sb + ASA(kt % 3), sb + ASB(kt % 3), wm * 64, wn * 64, lane, acc);
    }

    const int lrow = lane >> 2, lcol2 = (lane & 3) * 2;
    #pragma unroll
    for (int mi = 0; mi < 4; mi++) {
        const int gr0 = m0 + wm * 64 + mi * 16 + lrow;
        const int gr1 = gr0 + 8;
        const float iz0 = 1.0f / Z[(size_t)z * SDIM + gr0];
        const float iz1 = 1.0f / Z[(size_t)z * SDIM + gr1];
        #pragma unroll
        for (int ni = 0; ni < 8; ni++) {
            const int col = wn * 64 + ni * 8 + lcol2;
            __nv_bfloat162 h0 = __floats2bfloat162_rn(acc[mi][ni][0] * iz0, acc[mi][ni][1] * iz0);
            __nv_bfloat162 h1 = __floats2bfloat162_rn(acc[mi][ni][2] * iz1, acc[mi][ni][3] * iz1);
            *reinterpret_cast<uint32_t*>(y + ((size_t)z * SDIM + gr0) * CDIM + col) =
                *reinterpret_cast<uint32_t*>(&h0);
            *reinterpret_cast<uint32_t*>(y + ((size_t)z * SDIM + gr1) * CDIM + col) =
                *reinterpret_cast<uint32_t*>(&h1);
        }
    }
}

// ============================ projection + residual (bf16 HMMA) ============================
__global__ __launch_bounds__(256)
void proj_hmma(const __nv_bfloat16* __restrict__ w3,
               const __nv_bfloat16* __restrict__ y,
               const float* __restrict__ x,
               float* __restrict__ out)
{
    extern __shared__ char smem[];
    const uint32_t sb = smem_u32(smem);
    const int tid = threadIdx.x, lane = tid & 31, wid = tid >> 5;
    const int wm = wid & 1, wn = wid >> 1;
    const int z = blockIdx.z, m0 = blockIdx.y * 128, n0 = blockIdx.x * 128;

    const __nv_bfloat16* Abase = w3 + (size_t)m0 * 256;
    const __nv_bfloat16* Bbase = y + ((size_t)z * SDIM + n0) * CDIM;

    float acc[4][4][4];
    ZERO_ACC4(acc);

    load_tileT<128, 256>(sb + SA2(0), (const uint16_t*)Abase, 256);
    load_tileT<128, 256>(sb + SB2(0), (const uint16_t*)Bbase, 256);
    CP_COMMIT();

    const int KT = 4;
    #pragma unroll
    for (int kt = 0; kt < KT; kt++) {
        if (kt + 1 < KT) {
            load_tileT<128, 256>(sb + SA2((kt + 1) & 1), (const uint16_t*)(Abase + (kt + 1) * 64), 256);
            load_tileT<128, 256>(sb + SB2((kt + 1) & 1), (const uint16_t*)(Bbase + (kt + 1) * 64), 256);
            CP_COMMIT();
            CP_WAIT(1);
        } else {
            CP_WAIT(0);
        }
        __syncthreads();
        compute_chunk(sb + SA2(kt & 1), sb + SB2(kt & 1), wm * 64, wn * 32, lane, acc);
        __syncthreads();
    }

    const int lrow = lane >> 2, lcol2 = (lane & 3) * 2;
    #pragma unroll
    for (int mi = 0; mi < 4; mi++) {
        const int gr0 = m0 + wm * 64 + mi * 16 + lrow;
        const int gr1 = gr0 + 8;
        #pragma unroll
        for (int ni = 0; ni < 4; ni++) {
            const int col = n0 + wn * 32 + ni * 8 + lcol2;
            const float2 x0 = *reinterpret_cast<const float2*>(x + ((size_t)z * CDIM + gr0) * SDIM + col);
            const float2 x1 = *reinterpret_cast<const float2*>(x + ((size_t)z * CDIM + gr1) * SDIM + col);
            float2 v0 = make_float2(acc[mi][ni][0] + x0.x, acc[mi][ni][1] + x0.y);
            float2 v1 = make_float2(acc[mi][ni][2] + x1.x, acc[mi][ni][3] + x1.y);
            *reinterpret_cast<float2*>(out + ((size_t)z * CDIM + gr0) * SDIM + col) = v0;
            *reinterpret_cast<float2*>(out + ((size_t)z * CDIM + gr1) * SDIM + col) = v1;
        }
    }
}

// ============================ launch ============================
extern "C" void kernel_launch(void* const* d_in, const int* in_sizes, int n_in,
                              void* d_out, int out_size)
{
    const float* x       = (const float*)d_in[0];
    const float* theta_w = (const float*)d_in[1];
    const float* phi_w   = (const float*)d_in[2];
    const float* proj_w  = (const float*)d_in[3];
    float* out = (float*)d_out;

    uint16_t *tp8, *f8, *x8;
    __nv_bfloat16 *xb, *yb, *w2, *w3;
    float *Z;
    cudaGetSymbolAddress((void**)&tp8, g_tp8);
    cudaGetSymbolAddress((void**)&f8,  g_f8);
    cudaGetSymbolAddress((void**)&xb,  g_xb);
    cudaGetSymbolAddress((void**)&x8,  g_x8);
    cudaGetSymbolAddress((void**)&yb,  g_yb);
    cudaGetSymbolAddress((void**)&w2,  g_w2);
    cudaGetSymbolAddress((void**)&w3,  g_w3);
    cudaGetSymbolAddress((void**)&Z,   g_Z);

    cudaFuncSetAttribute(thetaphi_hmma, cudaFuncAttributeMaxDynamicSharedMemorySize, 65536);
    cudaFuncSetAttribute(logits_exp_f8, cudaFuncAttributeMaxDynamicSharedMemorySize, 49152);
    cudaFuncSetAttribute(attend_f8,     cudaFuncAttributeMaxDynamicSharedMemorySize, 147456);
    cudaFuncSetAttribute(proj_hmma,     cudaFuncAttributeMaxDynamicSharedMemorySize, 65536);

    // 0: conversions (bf16 + e4m3) + Z zero
    prep_bf16<<<1024, 256>>>((const float4*)x, (const float4*)theta_w, (const float4*)phi_w,
                             (const float4*)proj_w, (uint2*)xb, (uint32_t*)x8,
                             (uint2*)w2, (uint2*)w3, Z,
                             (int)((size_t)NBATCH * CDIM * SDIM / 4));

    // 1: fused theta+phi projection (bf16 in, e4m3 out)
    thetaphi_hmma<<<dim3(2, 32, 4), 256, 65536>>>(xb, w2, tp8);

    // 2: fused logits -> exp + row sums (FP8)
    logits_exp_f8<<<dim3(16, 32, 4), 256, 49152>>>(tp8, f8, Z);

    // 3: attend + 1/Z (FP8, single wave)
    attend_f8<<<dim3(1, 32, 4), 256, 147456>>>(f8, x8, Z, yb);

    // 4: projection + residual (bf16)
    proj_hmma<<<dim3(32, 2, 4), 256, 65536>>>(w3, yb, x, out);
}

// round 8
// speedup vs baseline: 1.1093x; 1.1093x over previous
#include <cuda_runtime.h>
#include <cuda_bf16.h>
#include <math.h>
#include <cstdint>

#define SDIM 4096
#define CDIM 256
#define EDIM 128
#define NBATCH 4

// ---- scratch (device globals: allocation-free) ----
__device__ __nv_bfloat16 g_tp[(size_t)NBATCH * SDIM * (2 * EDIM)]; // [n][s][0:128)=theta [128:256)=phi
__device__ __nv_bfloat16 g_f [(size_t)NBATCH * SDIM * SDIM];       // unnormalized exp(logits)
__device__ __nv_bfloat16 g_xb[(size_t)NBATCH * CDIM * SDIM];       // x bf16 [n][c][s]
__device__ __nv_bfloat16 g_yb[(size_t)NBATCH * SDIM * CDIM];       // y bf16 [n][s][c]
__device__ __nv_bfloat16 g_w2[256 * 256];                          // rows 0-127 theta_w, 128-255 phi_w
__device__ __nv_bfloat16 g_w3[256 * 256];                          // proj_w bf16 [o][c]
__device__ float         g_Z [(size_t)NBATCH * SDIM];              // row sums

// ============================ low-level helpers ============================
__device__ __forceinline__ uint32_t smem_u32(const void* p) {
    uint32_t a;
    asm("{ .reg .u64 t; cvta.to.shared.u64 t, %1; cvt.u32.u64 %0, t; }" : "=r"(a) : "l"(p));
    return a;
}
__device__ __forceinline__ void ldsm4(uint32_t r[4], uint32_t addr) {
    asm volatile("ldmatrix.sync.aligned.m8n8.x4.shared.b16 {%0,%1,%2,%3}, [%4];"
                 : "=r"(r[0]), "=r"(r[1]), "=r"(r[2]), "=r"(r[3]) : "r"(addr));
}
__device__ __forceinline__ void ldsm4t(uint32_t r[4], uint32_t addr) {
    asm volatile("ldmatrix.sync.aligned.m8n8.x4.trans.shared.b16 {%0,%1,%2,%3}, [%4];"
                 : "=r"(r[0]), "=r"(r[1]), "=r"(r[2]), "=r"(r[3]) : "r"(addr));
}
__device__ __forceinline__ void mma16816(float c[4], const uint32_t a[4], uint32_t b0, uint32_t b1) {
    asm volatile("mma.sync.aligned.m16n8k16.row.col.f32.bf16.bf16.f32 "
                 "{%0,%1,%2,%3},{%4,%5,%6,%7},{%8,%9},{%0,%1,%2,%3};"
                 : "+f"(c[0]), "+f"(c[1]), "+f"(c[2]), "+f"(c[3])
                 : "r"(a[0]), "r"(a[1]), "r"(a[2]), "r"(a[3]), "r"(b0), "r"(b1));
}
__device__ __forceinline__ void cp16(uint32_t saddr, const void* g) {
    asm volatile("cp.async.cg.shared.global [%0], [%1], 16;" :: "r"(saddr), "l"(g));
}
#define CP_COMMIT() asm volatile("cp.async.commit_group;" ::: "memory")
#define CP_WAIT(N)  asm volatile("cp.async.wait_group %0;" :: "n"(N) : "memory")

// R rows x 64 cols bf16 (128B rows), XOR-16B swizzle keyed on row&7. NT threads.
template<int R, int NT>
__device__ __forceinline__ void load_tileT(uint32_t sdst, const __nv_bfloat16* g, int ldg) {
    const int tid = threadIdx.x;
    #pragma unroll
    for (int i = 0; i < (R * 8) / NT; i++) {
        const int c = tid + i * NT;
        const int r = c >> 3, kc = c & 7;
        const uint32_t so = sdst + r * 128 + (((uint32_t)kc * 16) ^ ((r & 7) * 16));
        cp16(so, g + (size_t)r * ldg + kc * 8);
    }
}
// 64 rows x 128 cols bf16 (256B rows), 256 threads (trans-A path).
__device__ __forceinline__ void load_tile_64x128(uint32_t sdst, const __nv_bfloat16* g, int ldg) {
    const int tid = threadIdx.x;
    #pragma unroll
    for (int i = 0; i < 4; i++) {
        const int c = tid + i * 256;
        const int r = c >> 4, kc = c & 15;
        const uint32_t so = sdst + r * 256 + (((uint32_t)kc * 16) ^ ((r & 7) * 16));
        cp16(so, g + (size_t)r * ldg + kc * 8);
    }
}

// ---- 64x32 warp-tile chunk ----
__device__ __forceinline__ void compute_chunk(uint32_t sA, uint32_t sB,
                                              int m_base, int n_base, int lane,
                                              float acc[4][4][4]) {
    #pragma unroll
    for (int ks = 0; ks < 4; ks++) {
        const int kc = ks * 2 + (lane >> 4);
        uint32_t a[4][4];
        #pragma unroll
        for (int mi = 0; mi < 4; mi++) {
            const int row = m_base + mi * 16 + (lane & 15);
            ldsm4(a[mi], sA + row * 128 + (((uint32_t)kc * 16) ^ ((row & 7) * 16)));
        }
        uint32_t b[4][2];
        #pragma unroll
        for (int nh = 0; nh < 2; nh++) {
            const int row = n_base + nh * 16 + (lane & 15);
            uint32_t r4[4];
            ldsm4(r4, sB + row * 128 + (((uint32_t)kc * 16) ^ ((row & 7) * 16)));
            b[nh * 2 + 0][0] = r4[0]; b[nh * 2 + 0][1] = r4[2];
            b[nh * 2 + 1][0] = r4[1]; b[nh * 2 + 1][1] = r4[3];
        }
        #pragma unroll
        for (int mi = 0; mi < 4; mi++)
            #pragma unroll
            for (int ni = 0; ni < 4; ni++)
                mma16816(acc[mi][ni], a[mi], b[ni][0], b[ni][1]);
    }
}

// trans-A chunk (thetaphi)
__device__ __forceinline__ void compute_chunk_At(uint32_t sA, uint32_t sB,
                                                 int wm, int wn, int lane,
                                                 float acc[4][4][4]) {
    #pragma unroll
    for (int ks = 0; ks < 4; ks++) {
        uint32_t a[4][4];
        const int crow_l = ks * 16 + (lane & 7) + ((lane >> 4) & 1) * 8;
        #pragma unroll
        for (int mi = 0; mi < 4; mi++) {
            const int scol = wm * 64 + mi * 16 + ((lane >> 3) & 1) * 8;
            ldsm4t(a[mi], sA + crow_l * 256 + ((((uint32_t)scol >> 3) * 16) ^ ((crow_l & 7) * 16)));
        }
        const int kc = ks * 2 + (lane >> 4);
        uint32_t b[4][2];
        #pragma unroll
        for (int nh = 0; nh < 2; nh++) {
            const int row = wn * 32 + nh * 16 + (lane & 15);
            uint32_t r4[4];
            ldsm4(r4, sB + row * 128 + (((uint32_t)kc * 16) ^ ((row & 7) * 16)));
            b[nh * 2 + 0][0] = r4[0]; b[nh * 2 + 0][1] = r4[2];
            b[nh * 2 + 1][0] = r4[1]; b[nh * 2 + 1][1] = r4[3];
        }
        #pragma unroll
        for (int mi = 0; mi < 4; mi++)
            #pragma unroll
            for (int ni = 0; ni < 4; ni++)
                mma16816(acc[mi][ni], a[mi], b[ni][0], b[ni][1]);
    }
}

#define ZERO_ACC4(acc) do { \
    _Pragma("unroll") for (int _a = 0; _a < 4; _a++) \
    _Pragma("unroll") for (int _b = 0; _b < 4; _b++) \
    _Pragma("unroll") for (int _c = 0; _c < 4; _c++) acc[_a][_b][_c] = 0.0f; } while (0)

// ============================ prep ============================
__global__ __launch_bounds__(256) void prep_bf16(const float4* __restrict__ x,
                                                 const float4* __restrict__ theta_w,
                                                 const float4* __restrict__ phi_w,
                                                 const float4* __restrict__ proj_w,
                                                 uint2* __restrict__ xb,
                                                 uint2* __restrict__ w2,
                                                 uint2* __restrict__ w3,
                                                 float* __restrict__ Z, int n4)
{
    const int gt = blockIdx.x * blockDim.x + threadIdx.x;
    const int stride = gridDim.x * blockDim.x;
    if (gt < NBATCH * SDIM) Z[gt] = 0.0f;
    for (int i = gt; i < n4; i += stride) {
        float4 v = x[i];
        __nv_bfloat162 a = __floats2bfloat162_rn(v.x, v.y);
        __nv_bfloat162 b = __floats2bfloat162_rn(v.z, v.w);
        xb[i] = make_uint2(*reinterpret_cast<uint32_t*>(&a), *reinterpret_cast<uint32_t*>(&b));
    }
    if (gt < 8192) {
        float4 v = theta_w[gt];
        __nv_bfloat162 a = __floats2bfloat162_rn(v.x, v.y);
        __nv_bfloat162 b = __floats2bfloat162_rn(v.z, v.w);
        w2[gt] = make_uint2(*reinterpret_cast<uint32_t*>(&a), *reinterpret_cast<uint32_t*>(&b));
        v = phi_w[gt];
        a = __floats2bfloat162_rn(v.x, v.y);
        b = __floats2bfloat162_rn(v.z, v.w);
        w2[8192 + gt] = make_uint2(*reinterpret_cast<uint32_t*>(&a), *reinterpret_cast<uint32_t*>(&b));
    }
    if (gt < 16384) {
        float4 v = proj_w[gt];
        __nv_bfloat162 a = __floats2bfloat162_rn(v.x, v.y);
        __nv_bfloat162 b = __floats2bfloat162_rn(v.z, v.w);
        w3[gt] = make_uint2(*reinterpret_cast<uint32_t*>(&a), *reinterpret_cast<uint32_t*>(&b));
    }
}

// ============================ theta/phi projection (HMMA trans-A, 256 thr) ============================
#define SA2(st) ((uint32_t)((st) * 32768))
#define SB2(st) ((uint32_t)((st) * 32768 + 16384))
__global__ __launch_bounds__(256)
void thetaphi_hmma(const __nv_bfloat16* __restrict__ xb,
                   const __nv_bfloat16* __restrict__ w2,
                   __nv_bfloat16* __restrict__ tp)
{
    extern __shared__ char smem[];
    const uint32_t sb = smem_u32(smem);
    const int tid = threadIdx.x, lane = tid & 31, wid = tid >> 5;
    const int wm = wid & 1, wn = wid >> 1;
    const int z = blockIdx.z, m0 = blockIdx.y * 128, n0 = blockIdx.x * 128;

    const __nv_bfloat16* Abase = xb + (size_t)z * CDIM * SDIM + m0;
    const __nv_bfloat16* Bbase = w2 + (size_t)n0 * 256;

    float acc[4][4][4];
    ZERO_ACC4(acc);

    load_tile_64x128(sb + SA2(0), Abase, SDIM);
    load_tileT<128, 256>(sb + SB2(0), Bbase, 256);
    CP_COMMIT();

    const int KT = 4;
    #pragma unroll
    for (int kt = 0; kt < KT; kt++) {
        if (kt + 1 < KT) {
            load_tile_64x128(sb + SA2((kt + 1) & 1), Abase + (size_t)(kt + 1) * 64 * SDIM, SDIM);
            load_tileT<128, 256>(sb + SB2((kt + 1) & 1), Bbase + (kt + 1) * 64, 256);
            CP_COMMIT();
            CP_WAIT(1);
        } else {
            CP_WAIT(0);
        }
        __syncthreads();
        compute_chunk_At(sb + SA2(kt & 1), sb + SB2(kt & 1), wm, wn, lane, acc);
        __syncthreads();
    }

    const int lrow = lane >> 2, lcol2 = (lane & 3) * 2;
    #pragma unroll
    for (int mi = 0; mi < 4; mi++) {
        const int gr0 = m0 + wm * 64 + mi * 16 + lrow;
        #pragma unroll
        for (int ni = 0; ni < 4; ni++) {
            const int col = n0 + wn * 32 + ni * 8 + lcol2;
            __nv_bfloat162 h0 = __floats2bfloat162_rn(acc[mi][ni][0], acc[mi][ni][1]);
            __nv_bfloat162 h1 = __floats2bfloat162_rn(acc[mi][ni][2], acc[mi][ni][3]);
            *reinterpret_cast<uint32_t*>(tp + ((size_t)z * SDIM + gr0) * 256 + col) =
                *reinterpret_cast<uint32_t*>(&h0);
            *reinterpret_cast<uint32_t*>(tp + ((size_t)z * SDIM + gr0 + 8) * 256 + col) =
                *reinterpret_cast<uint32_t*>(&h1);
        }
    }
}

// ============================ fused logits + exp (theta-resident, 4 phi chunks, 3-buffer) ============================
// smem: theta A0 @0, A1 @16K (32KB). phi buffers st in {0,1,2}: chunk0 @32K+st*32K, chunk1 @+16K. 128KB total.
#define LTA(ch)     ((uint32_t)((ch) * 16384))
#define LPB(st, ch) ((uint32_t)(32768 + (st) * 32768 + (ch) * 16384))
__global__ __launch_bounds__(256)
void logits_exp_hmma(const __nv_bfloat16* __restrict__ tp,
                     __nv_bfloat16* __restrict__ f,
                     float* __restrict__ Z)
{
    extern __shared__ char smem[];
    const uint32_t sb = smem_u32(smem);
    const int tid = threadIdx.x, lane = tid & 31, wid = tid >> 5;
    const int wm = wid & 1, wn = wid >> 1;  // 2x4: 64x32 warp tiles over 128x128 S
    const int z = blockIdx.z, m0 = blockIdx.y * 128, n0 = blockIdx.x * 512;

    const __nv_bfloat16* Abase = tp + ((size_t)(z * SDIM + m0)) * 256;        // theta
    const __nv_bfloat16* Bbase = tp + ((size_t)(z * SDIM + n0)) * 256 + 128;  // phi (4 chunks of 128 rows)

    const float alpha = 0.08838834764831845f; // 1/sqrt(128)
    const int lrow = lane >> 2, lcol2 = (lane & 3) * 2;

    // prologue: theta (both K chunks) + phi chunk 0 -> group 0; phi chunk 1 -> group 1
    load_tileT<128, 256>(sb + LTA(0), Abase, 256);
    load_tileT<128, 256>(sb + LTA(1), Abase + 64, 256);
    load_tileT<128, 256>(sb + LPB(0, 0), Bbase, 256);
    load_tileT<128, 256>(sb + LPB(0, 1), Bbase + 64, 256);
    CP_COMMIT();
    load_tileT<128, 256>(sb + LPB(1, 0), Bbase + (size_t)128 * 256, 256);
    load_tileT<128, 256>(sb + LPB(1, 1), Bbase + (size_t)128 * 256 + 64, 256);
    CP_COMMIT();

    float zacc[8];  // per-thread partial row sums for 8 (mi, half) rows
    #pragma unroll
    for (int i = 0; i < 8; i++) zacc[i] = 0.0f;

    for (int p = 0; p < 4; p++) {
        if (p + 1 < 4) { CP_WAIT(1); } else { CP_WAIT(0); }
        __syncthreads();
        if (p + 2 < 4) {
            const int st = (p + 2) % 3;
            const __nv_bfloat16* pb = Bbase + (size_t)(p + 2) * 128 * 256;
            load_tileT<128, 256>(sb + LPB(st, 0), pb, 256);
            load_tileT<128, 256>(sb + LPB(st, 1), pb + 64, 256);
            CP_COMMIT();
        }
        float acc[4][4][4];
        ZERO_ACC4(acc);
        const int st = p % 3;
        compute_chunk(sb + LTA(0), sb + LPB(st, 0), wm * 64, wn * 32, lane, acc);
        compute_chunk(sb + LTA(1), sb + LPB(st, 1), wm * 64, wn * 32, lane, acc);

        // epilogue for this 128x128 tile (overlaps with in-flight cp.async)
        #pragma unroll
        for (int mi = 0; mi < 4; mi++) {
            const int gr0 = m0 + wm * 64 + mi * 16 + lrow;
            const int gr1 = gr0 + 8;
            #pragma unroll
            for (int ni = 0; ni < 4; ni++) {
                const int col = n0 + p * 128 + wn * 32 + ni * 8 + lcol2;
                float e00 = __expf(acc[mi][ni][0] * alpha);
                float e01 = __expf(acc[mi][ni][1] * alpha);
                float e10 = __expf(acc[mi][ni][2] * alpha);
                float e11 = __expf(acc[mi][ni][3] * alpha);
                zacc[mi * 2 + 0] += e00 + e01;
                zacc[mi * 2 + 1] += e10 + e11;
                __nv_bfloat162 h0 = __floats2bfloat162_rn(e00, e01);
                __nv_bfloat162 h1 = __floats2bfloat162_rn(e10, e11);
                *reinterpret_cast<uint32_t*>(f + ((size_t)z * SDIM + gr0) * SDIM + col) =
                    *reinterpret_cast<uint32_t*>(&h0);
                *reinterpret_cast<uint32_t*>(f + ((size_t)z * SDIM + gr1) * SDIM + col) =
                    *reinterpret_cast<uint32_t*>(&h1);
            }
        }
    }

    // Z atomics once per CTA (summed over all 4 tiles)
    #pragma unroll
    for (int mi = 0; mi < 4; mi++) {
        const int gr0 = m0 + wm * 64 + mi * 16 + lrow;
        float rs0 = zacc[mi * 2 + 0], rs1 = zacc[mi * 2 + 1];
        rs0 += __shfl_xor_sync(0xffffffffu, rs0, 1);
        rs0 += __shfl_xor_sync(0xffffffffu, rs0, 2);
        rs1 += __shfl_xor_sync(0xffffffffu, rs1, 1);
        rs1 += __shfl_xor_sync(0xffffffffu, rs1, 2);
        if ((lane & 3) == 0) {
            atomicAdd(&Z[(size_t)z * SDIM + gr0], rs0);
            atomicAdd(&Z[(size_t)z * SDIM + gr0 + 8], rs1);
        }
    }
}

// ============================ attend (R4-proven: 256 thr, 128x128 tiles, 3-stage) ============================
#define ASA(st) ((uint32_t)((st) * 32768))
#define ASB(st) ((uint32_t)((st) * 32768 + 16384))
__global__ __launch_bounds__(256)
void attend_hmma(const __nv_bfloat16* __restrict__ f,
                 const __nv_bfloat16* __restrict__ xb,
                 const float* __restrict__ Z,
                 __nv_bfloat16* __restrict__ y)
{
    extern __shared__ char smem[];
    const uint32_t sb = smem_u32(smem);
    const int tid = threadIdx.x, lane = tid & 31, wid = tid >> 5;
    const int wm = wid & 1, wn = wid >> 1;
    const int z = blockIdx.z, m0 = blockIdx.y * 128, n0 = blockIdx.x * 128;

    const __nv_bfloat16* Abase = f + ((size_t)z * SDIM + m0) * SDIM;
    const __nv_bfloat16* Bbase = xb + ((size_t)z * CDIM + n0) * SDIM;

    float acc[4][4][4];
    ZERO_ACC4(acc);

    load_tileT<128, 256>(sb + ASA(0), Abase, SDIM);
    load_tileT<128, 256>(sb + ASB(0), Bbase, SDIM);
    CP_COMMIT();
    load_tileT<128, 256>(sb + ASA(1), Abase + 64, SDIM);
    load_tileT<128, 256>(sb + ASB(1), Bbase + 64, SDIM);
    CP_COMMIT();

    const int KT = SDIM / 64; // 64
    for (int kt = 0; kt < KT; kt++) {
        if (kt + 1 < KT) { CP_WAIT(1); } else { CP_WAIT(0); }
        __syncthreads();
        if (kt + 2 < KT) {
            const int st = (kt + 2) % 3;
            load_tileT<128, 256>(sb + ASA(st), Abase + (kt + 2) * 64, SDIM);
            load_tileT<128, 256>(sb + ASB(st), Bbase + (kt + 2) * 64, SDIM);
            CP_COMMIT();
        }
        compute_chunk(sb + ASA(kt % 3), sb + ASB(kt % 3), wm * 64, wn * 32, lane, acc);
    }

    const int lrow = lane >> 2, lcol2 = (lane & 3) * 2;
    #pragma unroll
    for (int mi = 0; mi < 4; mi++) {
        const int gr0 = m0 + wm * 64 + mi * 16 + lrow;
        const int gr1 = gr0 + 8;
        const float iz0 = 1.0f / Z[(size_t)z * SDIM + gr0];
        const float iz1 = 1.0f / Z[(size_t)z * SDIM + gr1];
        #pragma unroll
        for (int ni = 0; ni < 4; ni++) {
            const int col = n0 + wn * 32 + ni * 8 + lcol2;
            __nv_bfloat162 h0 = __floats2bfloat162_rn(acc[mi][ni][0] * iz0, acc[mi][ni][1] * iz0);
            __nv_bfloat162 h1 = __floats2bfloat162_rn(acc[mi][ni][2] * iz1, acc[mi][ni][3] * iz1);
            *reinterpret_cast<uint32_t*>(y + ((size_t)z * SDIM + gr0) * CDIM + col) =
                *reinterpret_cast<uint32_t*>(&h0);
            *reinterpret_cast<uint32_t*>(y + ((size_t)z * SDIM + gr1) * CDIM + col) =
                *reinterpret_cast<uint32_t*>(&h1);
        }
    }
}

// ============================ projection + residual (HMMA, 256 thr) ============================
__global__ __launch_bounds__(256)
void proj_hmma(const __nv_bfloat16* __restrict__ w3,
               const __nv_bfloat16* __restrict__ y,
               const float* __restrict__ x,
               float* __restrict__ out)
{
    extern __shared__ char smem[];
    const uint32_t sb = smem_u32(smem);
    const int tid = threadIdx.x, lane = tid & 31, wid = tid >> 5;
    const int wm = wid & 1, wn = wid >> 1;
    const int z = blockIdx.z, m0 = blockIdx.y * 128, n0 = blockIdx.x * 128;

    const __nv_bfloat16* Abase = w3 + (size_t)m0 * 256;
    const __nv_bfloat16* Bbase = y + ((size_t)z * SDIM + n0) * CDIM;

    float acc[4][4][4];
    ZERO_ACC4(acc);

    load_tileT<128, 256>(sb + SA2(0), Abase, 256);
    load_tileT<128, 256>(sb + SB2(0), Bbase, 256);
    CP_COMMIT();

    const int KT = 4;
    #pragma unroll
    for (int kt = 0; kt < KT; kt++) {
        if (kt + 1 < KT) {
            load_tileT<128, 256>(sb + SA2((kt + 1) & 1), Abase + (kt + 1) * 64, 256);
            load_tileT<128, 256>(sb + SB2((kt + 1) & 1), Bbase + (kt + 1) * 64, 256);
            CP_COMMIT();
            CP_WAIT(1);
        } else {
            CP_WAIT(0);
        }
        __syncthreads();
        compute_chunk(sb + SA2(kt & 1), sb + SB2(kt & 1), wm * 64, wn * 32, lane, acc);
        __syncthreads();
    }

    const int lrow = lane >> 2, lcol2 = (lane & 3) * 2;
    #pragma unroll
    for (int mi = 0; mi < 4; mi++) {
        const int gr0 = m0 + wm * 64 + mi * 16 + lrow;
        const int gr1 = gr0 + 8;
        #pragma unroll
        for (int ni = 0; ni < 4; ni++) {
            const int col = n0 + wn * 32 + ni * 8 + lcol2;
            const float2 x0 = *reinterpret_cast<const float2*>(x + ((size_t)z * CDIM + gr0) * SDIM + col);
            const float2 x1 = *reinterpret_cast<const float2*>(x + ((size_t)z * CDIM + gr1) * SDIM + col);
            float2 v0 = make_float2(acc[mi][ni][0] + x0.x, acc[mi][ni][1] + x0.y);
            float2 v1 = make_float2(acc[mi][ni][2] + x1.x, acc[mi][ni][3] + x1.y);
            *reinterpret_cast<float2*>(out + ((size_t)z * CDIM + gr0) * SDIM + col) = v0;
            *reinterpret_cast<float2*>(out + ((size_t)z * CDIM + gr1) * SDIM + col) = v1;
        }
    }
}

// ============================ launch ============================
extern "C" void kernel_launch(void* const* d_in, const int* in_sizes, int n_in,
                              void* d_out, int out_size)
{
    const float* x       = (const float*)d_in[0];
    const float* theta_w = (const float*)d_in[1];
    const float* phi_w   = (const float*)d_in[2];
    const float* proj_w  = (const float*)d_in[3];
    float* out = (float*)d_out;

    __nv_bfloat16 *tp, *f, *xb, *yb, *w2, *w3;
    float *Z;
    cudaGetSymbolAddress((void**)&tp, g_tp);
    cudaGetSymbolAddress((void**)&f,  g_f);
    cudaGetSymbolAddress((void**)&xb, g_xb);
    cudaGetSymbolAddress((void**)&yb, g_yb);
    cudaGetSymbolAddress((void**)&w2, g_w2);
    cudaGetSymbolAddress((void**)&w3, g_w3);
    cudaGetSymbolAddress((void**)&Z,  g_Z);

    cudaFuncSetAttribute(thetaphi_hmma,   cudaFuncAttributeMaxDynamicSharedMemorySize, 65536);
    cudaFuncSetAttribute(logits_exp_hmma, cudaFuncAttributeMaxDynamicSharedMemorySize, 131072);
    cudaFuncSetAttribute(attend_hmma,     cudaFuncAttributeMaxDynamicSharedMemorySize, 98304);
    cudaFuncSetAttribute(proj_hmma,       cudaFuncAttributeMaxDynamicSharedMemorySize, 65536);

    // 0: bf16 conversions + Z zero
    prep_bf16<<<1024, 256>>>((const float4*)x, (const float4*)theta_w, (const float4*)phi_w,
                             (const float4*)proj_w, (uint2*)xb, (uint2*)w2, (uint2*)w3, Z,
                             (int)((size_t)NBATCH * CDIM * SDIM / 4));

    // 1: fused theta+phi projection
    thetaphi_hmma<<<dim3(2, 32, 4), 256, 65536>>>(xb, w2, tp);

    // 2: fused logits -> exp + row sums (theta-resident, 128x512 per CTA)
    logits_exp_hmma<<<dim3(8, 32, 4), 256, 131072>>>(tp, f, Z);

    // 3: attend + 1/Z (R4-proven config)
    attend_hmma<<<dim3(2, 32, 4), 256, 98304>>>(f, xb, Z, yb);

    // 4: projection + residual
    proj_hmma<<<dim3(32, 2, 4), 256, 65536>>>(w3, yb, x, out);
}

// round 9
// speedup vs baseline: 1.1927x; 1.0752x over previous
#include <cuda_runtime.h>
#include <cuda_bf16.h>
#include <math.h>
#include <cstdint>

#define SDIM 4096
#define CDIM 256
#define EDIM 128
#define NBATCH 4

// ---- scratch (device globals: allocation-free) ----
// tp rows = spatial s/t, 512 cols: [0:128)=theta, [128:256)=phi, [256:512)=xp^T (= (proj_w@x)[o,t])
__device__ __nv_bfloat16 g_tp[(size_t)NBATCH * SDIM * 512];
__device__ __nv_bfloat16 g_f [(size_t)NBATCH * SDIM * SDIM];       // unnormalized exp(logits)
__device__ __nv_bfloat16 g_xb[(size_t)NBATCH * CDIM * SDIM];       // x bf16 [n][c][s]
__device__ __nv_bfloat16 g_w2[512 * 256];                          // rows: 0-127 theta_w, 128-255 phi_w, 256-511 proj_w
__device__ float         g_Z [(size_t)NBATCH * SDIM];              // row sums

// ============================ low-level helpers ============================
__device__ __forceinline__ uint32_t smem_u32(const void* p) {
    uint32_t a;
    asm("{ .reg .u64 t; cvta.to.shared.u64 t, %1; cvt.u32.u64 %0, t; }" : "=r"(a) : "l"(p));
    return a;
}
__device__ __forceinline__ void ldsm4(uint32_t r[4], uint32_t addr) {
    asm volatile("ldmatrix.sync.aligned.m8n8.x4.shared.b16 {%0,%1,%2,%3}, [%4];"
                 : "=r"(r[0]), "=r"(r[1]), "=r"(r[2]), "=r"(r[3]) : "r"(addr));
}
__device__ __forceinline__ void ldsm4t(uint32_t r[4], uint32_t addr) {
    asm volatile("ldmatrix.sync.aligned.m8n8.x4.trans.shared.b16 {%0,%1,%2,%3}, [%4];"
                 : "=r"(r[0]), "=r"(r[1]), "=r"(r[2]), "=r"(r[3]) : "r"(addr));
}
__device__ __forceinline__ void mma16816(float c[4], const uint32_t a[4], uint32_t b0, uint32_t b1) {
    asm volatile("mma.sync.aligned.m16n8k16.row.col.f32.bf16.bf16.f32 "
                 "{%0,%1,%2,%3},{%4,%5,%6,%7},{%8,%9},{%0,%1,%2,%3};"
                 : "+f"(c[0]), "+f"(c[1]), "+f"(c[2]), "+f"(c[3])
                 : "r"(a[0]), "r"(a[1]), "r"(a[2]), "r"(a[3]), "r"(b0), "r"(b1));
}
__device__ __forceinline__ void cp16(uint32_t saddr, const void* g) {
    asm volatile("cp.async.cg.shared.global [%0], [%1], 16;" :: "r"(saddr), "l"(g));
}
#define CP_COMMIT() asm volatile("cp.async.commit_group;" ::: "memory")
#define CP_WAIT(N)  asm volatile("cp.async.wait_group %0;" :: "n"(N) : "memory")

// R rows x 64 cols bf16 (128B rows), XOR-16B swizzle keyed on row&7. NT threads.
template<int R, int NT>
__device__ __forceinline__ void load_tileT(uint32_t sdst, const __nv_bfloat16* g, int ldg) {
    const int tid = threadIdx.x;
    #pragma unroll
    for (int i = 0; i < (R * 8) / NT; i++) {
        const int c = tid + i * NT;
        const int r = c >> 3, kc = c & 7;
        const uint32_t so = sdst + r * 128 + (((uint32_t)kc * 16) ^ ((r & 7) * 16));
        cp16(so, g + (size_t)r * ldg + kc * 8);
    }
}
// 64 rows x 128 cols bf16 (256B rows), 256 threads (trans-A operand tile).
__device__ __forceinline__ void load_tile_64x128(uint32_t sdst, const __nv_bfloat16* g, int ldg) {
    const int tid = threadIdx.x;
    #pragma unroll
    for (int i = 0; i < 4; i++) {
        const int c = tid + i * 256;
        const int r = c >> 4, kc = c & 15;
        const uint32_t so = sdst + r * 256 + (((uint32_t)kc * 16) ^ ((r & 7) * 16));
        cp16(so, g + (size_t)r * ldg + kc * 8);
    }
}

// ---- 64x32 warp-tile chunk (regular A) ----
__device__ __forceinline__ void compute_chunk(uint32_t sA, uint32_t sB,
                                              int m_base, int n_base, int lane,
                                              float acc[4][4][4]) {
    #pragma unroll
    for (int ks = 0; ks < 4; ks++) {
        const int kc = ks * 2 + (lane >> 4);
        uint32_t a[4][4];
        #pragma unroll
        for (int mi = 0; mi < 4; mi++) {
            const int row = m_base + mi * 16 + (lane & 15);
            ldsm4(a[mi], sA + row * 128 + (((uint32_t)kc * 16) ^ ((row & 7) * 16)));
        }
        uint32_t b[4][2];
        #pragma unroll
        for (int nh = 0; nh < 2; nh++) {
            const int row = n_base + nh * 16 + (lane & 15);
            uint32_t r4[4];
            ldsm4(r4, sB + row * 128 + (((uint32_t)kc * 16) ^ ((row & 7) * 16)));
            b[nh * 2 + 0][0] = r4[0]; b[nh * 2 + 0][1] = r4[2];
            b[nh * 2 + 1][0] = r4[1]; b[nh * 2 + 1][1] = r4[3];
        }
        #pragma unroll
        for (int mi = 0; mi < 4; mi++)
            #pragma unroll
            for (int ni = 0; ni < 4; ni++)
                mma16816(acc[mi][ni], a[mi], b[ni][0], b[ni][1]);
    }
}

// ---- trans-A chunk: A stored [k][m] (64 rows x 128 cols, 256B rows), B regular [n][k] ----
__device__ __forceinline__ void compute_chunk_At(uint32_t sA, uint32_t sB,
                                                 int wm, int wn, int lane,
                                                 float acc[4][4][4]) {
    #pragma unroll
    for (int ks = 0; ks < 4; ks++) {
        uint32_t a[4][4];
        const int crow_l = ks * 16 + (lane & 7) + ((lane >> 4) & 1) * 8;
        #pragma unroll
        for (int mi = 0; mi < 4; mi++) {
            const int scol = wm * 64 + mi * 16 + ((lane >> 3) & 1) * 8;
            ldsm4t(a[mi], sA + crow_l * 256 + ((((uint32_t)scol >> 3) * 16) ^ ((crow_l & 7) * 16)));
        }
        const int kc = ks * 2 + (lane >> 4);
        uint32_t b[4][2];
        #pragma unroll
        for (int nh = 0; nh < 2; nh++) {
            const int row = wn * 32 + nh * 16 + (lane & 15);
            uint32_t r4[4];
            ldsm4(r4, sB + row * 128 + (((uint32_t)kc * 16) ^ ((row & 7) * 16)));
            b[nh * 2 + 0][0] = r4[0]; b[nh * 2 + 0][1] = r4[2];
            b[nh * 2 + 1][0] = r4[1]; b[nh * 2 + 1][1] = r4[3];
        }
        #pragma unroll
        for (int mi = 0; mi < 4; mi++)
            #pragma unroll
            for (int ni = 0; ni < 4; ni++)
                mma16816(acc[mi][ni], a[mi], b[ni][0], b[ni][1]);
    }
}

#define ZERO_ACC4(acc) do { \
    _Pragma("unroll") for (int _a = 0; _a < 4; _a++) \
    _Pragma("unroll") for (int _b = 0; _b < 4; _b++) \
    _Pragma("unroll") for (int _c = 0; _c < 4; _c++) acc[_a][_b][_c] = 0.0f; } while (0)

// ============================ prep ============================
__global__ __launch_bounds__(256) void prep_bf16(const float4* __restrict__ x,
                                                 const float4* __restrict__ theta_w,
                                                 const float4* __restrict__ phi_w,
                                                 const float4* __restrict__ proj_w,
                                                 uint2* __restrict__ xb,
                                                 uint2* __restrict__ w2,
                                                 float* __restrict__ Z, int n4)
{
    const int gt = blockIdx.x * blockDim.x + threadIdx.x;
    const int stride = gridDim.x * blockDim.x;
    if (gt < NBATCH * SDIM) Z[gt] = 0.0f;
    for (int i = gt; i < n4; i += stride) {
        float4 v = x[i];
        __nv_bfloat162 a = __floats2bfloat162_rn(v.x, v.y);
        __nv_bfloat162 b = __floats2bfloat162_rn(v.z, v.w);
        xb[i] = make_uint2(*reinterpret_cast<uint32_t*>(&a), *reinterpret_cast<uint32_t*>(&b));
    }
    if (gt < 8192) {        // theta_w, phi_w: 128x256 each
        float4 v = theta_w[gt];
        __nv_bfloat162 a = __floats2bfloat162_rn(v.x, v.y);
        __nv_bfloat162 b = __floats2bfloat162_rn(v.z, v.w);
        w2[gt] = make_uint2(*reinterpret_cast<uint32_t*>(&a), *reinterpret_cast<uint32_t*>(&b));
        v = phi_w[gt];
        a = __floats2bfloat162_rn(v.x, v.y);
        b = __floats2bfloat162_rn(v.z, v.w);
        w2[8192 + gt] = make_uint2(*reinterpret_cast<uint32_t*>(&a), *reinterpret_cast<uint32_t*>(&b));
    }
    if (gt < 16384) {       // proj_w: 256x256 -> w2 rows 256-511
        float4 v = proj_w[gt];
        __nv_bfloat162 a = __floats2bfloat162_rn(v.x, v.y);
        __nv_bfloat162 b = __floats2bfloat162_rn(v.z, v.w);
        w2[16384 + gt] = make_uint2(*reinterpret_cast<uint32_t*>(&a), *reinterpret_cast<uint32_t*>(&b));
    }
}

// ============================ projections (HMMA trans-A): tp[s][o] = sum_c xb[c,s] * w2[o,c] ============================
// Covers theta (o 0-127), phi (128-255), xp^T (256-511). grid (4 o-tiles, 32 s-tiles, 4).
#define SA2(st) ((uint32_t)((st) * 32768))
#define SB2(st) ((uint32_t)((st) * 32768 + 16384))
__global__ __launch_bounds__(256)
void projections_hmma(const __nv_bfloat16* __restrict__ xb,
                      const __nv_bfloat16* __restrict__ w2,
                      __nv_bfloat16* __restrict__ tp)
{
    extern __shared__ char smem[];
    const uint32_t sb = smem_u32(smem);
    const int tid = threadIdx.x, lane = tid & 31, wid = tid >> 5;
    const int wm = wid & 1, wn = wid >> 1;
    const int z = blockIdx.z, m0 = blockIdx.y * 128, n0 = blockIdx.x * 128;

    const __nv_bfloat16* Abase = xb + (size_t)z * CDIM * SDIM + m0;
    const __nv_bfloat16* Bbase = w2 + (size_t)n0 * 256;

    float acc[4][4][4];
    ZERO_ACC4(acc);

    load_tile_64x128(sb + SA2(0), Abase, SDIM);
    load_tileT<128, 256>(sb + SB2(0), Bbase, 256);
    CP_COMMIT();

    const int KT = 4;
    #pragma unroll
    for (int kt = 0; kt < KT; kt++) {
        if (kt + 1 < KT) {
            load_tile_64x128(sb + SA2((kt + 1) & 1), Abase + (size_t)(kt + 1) * 64 * SDIM, SDIM);
            load_tileT<128, 256>(sb + SB2((kt + 1) & 1), Bbase + (kt + 1) * 64, 256);
            CP_COMMIT();
            CP_WAIT(1);
        } else {
            CP_WAIT(0);
        }
        __syncthreads();
        compute_chunk_At(sb + SA2(kt & 1), sb + SB2(kt & 1), wm, wn, lane, acc);
        __syncthreads();
    }

    const int lrow = lane >> 2, lcol2 = (lane & 3) * 2;
    #pragma unroll
    for (int mi = 0; mi < 4; mi++) {
        const int gr0 = m0 + wm * 64 + mi * 16 + lrow;   // s
        #pragma unroll
        for (int ni = 0; ni < 4; ni++) {
            const int col = n0 + wn * 32 + ni * 8 + lcol2;  // o in [0,512)
            __nv_bfloat162 h0 = __floats2bfloat162_rn(acc[mi][ni][0], acc[mi][ni][1]);
            __nv_bfloat162 h1 = __floats2bfloat162_rn(acc[mi][ni][2], acc[mi][ni][3]);
            *reinterpret_cast<uint32_t*>(tp + ((size_t)z * SDIM + gr0) * 512 + col) =
                *reinterpret_cast<uint32_t*>(&h0);
            *reinterpret_cast<uint32_t*>(tp + ((size_t)z * SDIM + gr0 + 8) * 512 + col) =
                *reinterpret_cast<uint32_t*>(&h1);
        }
    }
}

// ============================ fused logits + exp (R4-proven shape, ld=512) ============================
__global__ __launch_bounds__(256)
void logits_exp_hmma(const __nv_bfloat16* __restrict__ tp,
                     __nv_bfloat16* __restrict__ f,
                     float* __restrict__ Z)
{
    extern __shared__ char smem[];
    const uint32_t sb = smem_u32(smem);
    const int tid = threadIdx.x, lane = tid & 31, wid = tid >> 5;
    const int wm = wid & 1, wn = wid >> 1;
    const int z = blockIdx.z, m0 = blockIdx.y * 128, n0 = blockIdx.x * 128;

    const __nv_bfloat16* Abase = tp + ((size_t)(z * SDIM + m0)) * 512;        // theta
    const __nv_bfloat16* Bbase = tp + ((size_t)(z * SDIM + n0)) * 512 + 128;  // phi

    float acc[4][4][4];
    ZERO_ACC4(acc);

    load_tileT<128, 256>(sb + SA2(0), Abase, 512);
    load_tileT<128, 256>(sb + SB2(0), Bbase, 512);
    CP_COMMIT();
    load_tileT<128, 256>(sb + SA2(1), Abase + 64, 512);
    load_tileT<128, 256>(sb + SB2(1), Bbase + 64, 512);
    CP_COMMIT();

    CP_WAIT(1);
    __syncthreads();
    compute_chunk(sb + SA2(0), sb + SB2(0), wm * 64, wn * 32, lane, acc);
    CP_WAIT(0);
    __syncthreads();
    compute_chunk(sb + SA2(1), sb + SB2(1), wm * 64, wn * 32, lane, acc);

    const float alpha = 0.08838834764831845f; // 1/sqrt(128)
    const int lrow = lane >> 2, lcol2 = (lane & 3) * 2;
    #pragma unroll
    for (int mi = 0; mi < 4; mi++) {
        const int gr0 = m0 + wm * 64 + mi * 16 + lrow;
        const int gr1 = gr0 + 8;
        float rs0 = 0.0f, rs1 = 0.0f;
        #pragma unroll
        for (int ni = 0; ni < 4; ni++) {
            const int col = n0 + wn * 32 + ni * 8 + lcol2;
            float e00 = __expf(acc[mi][ni][0] * alpha);
            float e01 = __expf(acc[mi][ni][1] * alpha);
            float e10 = __expf(acc[mi][ni][2] * alpha);
            float e11 = __expf(acc[mi][ni][3] * alpha);
            rs0 += e00 + e01; rs1 += e10 + e11;
            __nv_bfloat162 h0 = __floats2bfloat162_rn(e00, e01);
            __nv_bfloat162 h1 = __floats2bfloat162_rn(e10, e11);
            *reinterpret_cast<uint32_t*>(f + ((size_t)z * SDIM + gr0) * SDIM + col) =
                *reinterpret_cast<uint32_t*>(&h0);
            *reinterpret_cast<uint32_t*>(f + ((size_t)z * SDIM + gr1) * SDIM + col) =
                *reinterpret_cast<uint32_t*>(&h1);
        }
        rs0 += __shfl_xor_sync(0xffffffffu, rs0, 1);
        rs0 += __shfl_xor_sync(0xffffffffu, rs0, 2);
        rs1 += __shfl_xor_sync(0xffffffffu, rs1, 1);
        rs1 += __shfl_xor_sync(0xffffffffu, rs1, 2);
        if ((lane & 3) == 0) {
            atomicAdd(&Z[(size_t)z * SDIM + gr0], rs0);
            atomicAdd(&Z[(size_t)z * SDIM + gr1], rs1);
        }
    }
}

// ============================ fused attend+proj (trans-A HMMA, 3-stage) ============================
// out[n][o][s] = x[n][o][s] + (1/Z[s]) * sum_t xp[o,t] * f[s,t]
//   A (trans) = tp[t][256+o] chunks [64t x 128o], B = f[s][t] chunks [128s x 64t].
// grid (32 s-tiles, 2 o-tiles, 4 batches), 256 thr, 96KB smem (2 CTAs/SM).
#define ASA(st) ((uint32_t)((st) * 32768))
#define ASB(st) ((uint32_t)((st) * 32768 + 16384))
__global__ __launch_bounds__(256)
void attend_proj_hmma(const __nv_bfloat16* __restrict__ tp,
                      const __nv_bfloat16* __restrict__ f,
                      const float* __restrict__ Z,
                      const float* __restrict__ x,
                      float* __restrict__ out)
{
    extern __shared__ char smem[];
    const uint32_t sb = smem_u32(smem);
    const int tid = threadIdx.x, lane = tid & 31, wid = tid >> 5;
    const int wm = wid & 1, wn = wid >> 1;
    const int z = blockIdx.z, m0 = blockIdx.y * 128, n0 = blockIdx.x * 128;

    const __nv_bfloat16* Abase = tp + (size_t)z * SDIM * 512 + 256 + m0;   // rows t, ld 512
    const __nv_bfloat16* Bbase = f + ((size_t)z * SDIM + n0) * SDIM;       // rows s, ld SDIM

    float acc[4][4][4];
    ZERO_ACC4(acc);

    load_tile_64x128(sb + ASA(0), Abase, 512);
    load_tileT<128, 256>(sb + ASB(0), Bbase, SDIM);
    CP_COMMIT();
    load_tile_64x128(sb + ASA(1), Abase + (size_t)64 * 512, 512);
    load_tileT<128, 256>(sb + ASB(1), Bbase + 64, SDIM);
    CP_COMMIT();

    const int KT = SDIM / 64; // 64
    for (int kt = 0; kt < KT; kt++) {
        if (kt + 1 < KT) { CP_WAIT(1); } else { CP_WAIT(0); }
        __syncthreads();
        if (kt + 2 < KT) {
            const int st = (kt + 2) % 3;
            load_tile_64x128(sb + ASA(st), Abase + (size_t)(kt + 2) * 64 * 512, 512);
            load_tileT<128, 256>(sb + ASB(st), Bbase + (kt + 2) * 64, SDIM);
            CP_COMMIT();
        }
        compute_chunk_At(sb + ASA(kt % 3), sb + ASB(kt % 3), wm, wn, lane, acc);
    }

    // epilogue: rows = o, cols = s; scale by 1/Z[s], add residual x, fp32 out
    const int lrow = lane >> 2, lcol2 = (lane & 3) * 2;
    #pragma unroll
    for (int ni = 0; ni < 4; ni++) {
        const int col = n0 + wn * 32 + ni * 8 + lcol2;   // s (even)
        const float2 zc = *reinterpret_cast<const float2*>(&Z[(size_t)z * SDIM + col]);
        const float izx = 1.0f / zc.x, izy = 1.0f / zc.y;
        #pragma unroll
        for (int mi = 0; mi < 4; mi++) {
            const int gr0 = m0 + wm * 64 + mi * 16 + lrow;   // o
            const int gr1 = gr0 + 8;
            const float2 x0 = *reinterpret_cast<const float2*>(x + ((size_t)z * CDIM + gr0) * SDIM + col);
            const float2 x1 = *reinterpret_cast<const float2*>(x + ((size_t)z * CDIM + gr1) * SDIM + col);
            float2 v0 = make_float2(acc[mi][ni][0] * izx + x0.x, acc[mi][ni][1] * izy + x0.y);
            float2 v1 = make_float2(acc[mi][ni][2] * izx + x1.x, acc[mi][ni][3] * izy + x1.y);
            *reinterpret_cast<float2*>(out + ((size_t)z * CDIM + gr0) * SDIM + col) = v0;
            *reinterpret_cast<float2*>(out + ((size_t)z * CDIM + gr1) * SDIM + col) = v1;
        }
    }
}

// ============================ launch ============================
extern "C" void kernel_launch(void* const* d_in, const int* in_sizes, int n_in,
                              void* d_out, int out_size)
{
    const float* x       = (const float*)d_in[0];
    const float* theta_w = (const float*)d_in[1];
    const float* phi_w   = (const float*)d_in[2];
    const float* proj_w  = (const float*)d_in[3];
    float* out = (float*)d_out;

    __nv_bfloat16 *tp, *f, *xb, *w2;
    float *Z;
    cudaGetSymbolAddress((void**)&tp, g_tp);
    cudaGetSymbolAddress((void**)&f,  g_f);
    cudaGetSymbolAddress((void**)&xb, g_xb);
    cudaGetSymbolAddress((void**)&w2, g_w2);
    cudaGetSymbolAddress((void**)&Z,  g_Z);

    cudaFuncSetAttribute(projections_hmma, cudaFuncAttributeMaxDynamicSharedMemorySize, 65536);
    cudaFuncSetAttribute(logits_exp_hmma,  cudaFuncAttributeMaxDynamicSharedMemorySize, 65536);
    cudaFuncSetAttribute(attend_proj_hmma, cudaFuncAttributeMaxDynamicSharedMemorySize, 98304);

    // 0: bf16 conversions + Z zero
    prep_bf16<<<1024, 256>>>((const float4*)x, (const float4*)theta_w, (const float4*)phi_w,
                             (const float4*)proj_w, (uint2*)xb, (uint2*)w2, Z,
                             (int)((size_t)NBATCH * CDIM * SDIM / 4));

    // 1: all three projections (theta, phi, xp = proj_w @ x) in one GEMM
    projections_hmma<<<dim3(4, 32, 4), 256, 65536>>>(xb, w2, tp);

    // 2: fused logits -> exp + row sums (R4-proven shape)
    logits_exp_hmma<<<dim3(32, 32, 4), 256, 65536>>>(tp, f, Z);

    // 3: fused attend + projection + residual + 1/Z
    attend_proj_hmma<<<dim3(32, 2, 4), 256, 98304>>>(tp, f, Z, x, out);
}